// round 9
// baseline (speedup 1.0000x reference)
#include <cuda_runtime.h>
#include <cuda_fp16.h>
#include <cstdint>

// Problem constants (fixed per reference)
#define Bn 8
#define Hn 1080
#define Wn 1920
constexpr int HW   = Hn * Wn;          // 2,073,600
constexpr int BHW  = Bn * HW;          // 16,588,800
constexpr int WP   = Wn / 2;           // 960 pair-cells per row
constexpr int LAT1 = Hn * WP;          // 1,036,800 pair-cells per parity lattice

// Per-slice pair-cell lattices (REUSED for all 8 batches -> L2-resident):
// 16B cell = [vx0,vy0,vx1,vy1 (4xf16) | w0,w1 (2xf16) | pad (4B)]
// Deposit = 8B v2.f16x2 RED (xy, both corners) + 4B f16x2 RED (w, both corners)
//           -> 24B useful payload per pixel (no pad halves through the LTS ALU).
// Parity 0 (even): pair k covers corners (2k, 2k+1)
// Parity 1 (odd):  pair k covers corners (2k+1, 2k+2)  [hi of last pair: trash, never read]
__device__ float4        g_lat[2 * LAT1];   // 33.2 MB — fits L2 (126 MB)
__device__ unsigned char g_mask[BHW];       // count>0 flag (whole image)
__device__ int           g_holes[BHW];      // compacted hole indices (global index)
__device__ int           g_hole_count;

// --- bit reinterpretation helpers (header-portable) ------------------------
__device__ __forceinline__ unsigned h2_to_u32(__half2 h) {
    union { __half2 h; unsigned u; } cvt; cvt.h = h; return cvt.u;
}
__device__ __forceinline__ __half2 u32_to_h2(unsigned u) {
    union { unsigned u; __half2 h; } cvt; cvt.u = u; return cvt.h;
}

// 8B vector f16x2 reduction (xy payload for two corners)
__device__ __forceinline__ void red_v2(void* p, unsigned r0, unsigned r1) {
    asm volatile("red.global.add.noftz.v2.f16x2 [%0], {%1, %2};"
                 :: "l"(p), "r"(r0), "r"(r1) : "memory");
}
// 4B scalar f16x2 reduction (w payload for two corners)
__device__ __forceinline__ void red_s(void* p, unsigned r) {
    asm volatile("red.global.add.noftz.f16x2 [%0], %1;"
                 :: "l"(p), "r"(r) : "memory");
}

// ---------------------------------------------------------------------------
// 1) Zero the slice lattices (+ hole counter once per replay).
//    Full-line writes also restore L2 residency of the slot (R7 lesson).
//    Grid covers 2*LAT1 == HW exactly (8100 x 256).
// ---------------------------------------------------------------------------
__global__ void zero_kernel(int reset_counter) {
    int i = blockIdx.x * blockDim.x + threadIdx.x;
    g_lat[i] = make_float4(0.f, 0.f, 0.f, 0.f);
    if (reset_counter && i == 0) g_hole_count = 0;
}

// ---------------------------------------------------------------------------
// 2) Forward splat for ONE batch slice: per target row, one 8B xy-RED +
//    one 4B w-RED into the SAME 16B cell (same 32B sector).
//    flow/depth pointers pre-offset to this batch.
// ---------------------------------------------------------------------------
__global__ void splat_kernel(const float* __restrict__ flow,
                             const float* __restrict__ depth) {
    const int p = blockIdx.x * blockDim.x + threadIdx.x;   // [0, HW)
    const int y = p / Wn;
    const int x = p - y * Wn;

    const float fx = flow[p];
    const float fy = flow[HW + p];

    const float x2 = (float)x + fx;
    const float y2 = (float)y + fy;

    // Invalid pixels deposit exactly 0 in the reference -> skip.
    if (!(x2 >= 0.0f && x2 <= (float)(Wn - 1) &&
          y2 >= 0.0f && y2 <= (float)(Hn - 1)))
        return;

    const float w  = depth[p];
    const float vx = -fx * w;
    const float vy = -fy * w;

    // floor == trunc (non-negative by validity check)
    const int ixL = (int)x2;
    const int iyT = (int)y2;
    const int ixR = min(ixL + 1, Wn - 1);
    const int iyB = min(iyT + 1, Hn - 1);

    // xy payload: reg0 -> corner L (bytes 0-3), reg1 -> corner R (bytes 4-7)
    // w payload:  f16x2 (wL, wR) at cell offset 8.
    // Dup case (x2 == W-1 exactly, odd lattice last pair): double lo, zero hi
    // (rn(2v) == 2*rn(v) in f16, bit-identical to two adds).
    const bool  dup = (ixR == ixL);
    const float m   = dup ? 2.0f : 1.0f;

    const unsigned xyL = h2_to_u32(__floats2half2_rn(vx * m, vy * m));
    const unsigned xyR = dup ? 0u : h2_to_u32(__floats2half2_rn(vx, vy));
    const unsigned wLR = h2_to_u32(__floats2half2_rn(w * m, dup ? 0.0f : w));

    const int s  = ixL & 1;        // lattice parity
    const int kp = ixL >> 1;       // pair index

    char* lat = (char*)(g_lat + (size_t)s * LAT1 + kp);
    char* cT  = lat + (size_t)iyT * (WP * 16);
    char* cB  = lat + (size_t)iyB * (WP * 16);
    red_v2(cT,     xyL, xyR);
    red_s (cT + 8, wLR);
    red_v2(cB,     xyL, xyR);
    red_s (cB + 8, wLR);
}

// ---------------------------------------------------------------------------
// 3) Normalize ONE batch slice: load the even + odd 16B cells (pairwise-
//    duplicate across threads -> L1 broadcast, no extra wavefronts), extract
//    this pixel's half, divide, write out slice, mask, compact holes.
// ---------------------------------------------------------------------------
__global__ void normalize_kernel(float* __restrict__ out, int gbase) {
    const int p = blockIdx.x * blockDim.x + threadIdx.x;   // [0, HW)
    const int y = p / Wn;
    const int x = p - y * Wn;

    const uint4* lat = (const uint4*)g_lat;
    const size_t rowc = (size_t)y * WP;

    // Even-lattice cell: pair x>>1, half x&1
    const int he = x & 1;
    const uint4 e = lat[rowc + (x >> 1)];
    const float2 xyE = __half22float2(u32_to_h2(he ? e.y : e.x));
    const __half2 ewz = u32_to_h2(e.z);
    const float  wE  = he ? __high2float(ewz) : __low2float(ewz);

    // Odd-lattice cell: covers x >= 1
    float2 xyO = make_float2(0.f, 0.f);
    float  wO  = 0.f;
    if (x > 0) {
        const int xo = x - 1;
        const int ho = xo & 1;
        const uint4 o = lat[(size_t)LAT1 + rowc + (xo >> 1)];
        xyO = __half22float2(u32_to_h2(ho ? o.y : o.x));
        const __half2 owz = u32_to_h2(o.z);
        wO = ho ? __high2float(owz) : __low2float(owz);
    }

    const float cnt  = wE + wO;
    const bool  hole = !(cnt > 0.0f);
    const float inv  = 1.0f / (hole ? 1.0f : cnt);

    out[p]      = (xyE.x + xyO.x) * inv;
    out[HW + p] = (xyE.y + xyO.y) * inv;
    g_mask[gbase + p] = hole ? 0 : 1;

    // Compact hole indices: one atomicAdd per warp.
    const unsigned ballot = __ballot_sync(0xffffffffu, hole);
    if (ballot) {
        const int lane   = threadIdx.x & 31;
        const int leader = __ffs(ballot) - 1;
        int base = 0;
        if (lane == leader) base = atomicAdd(&g_hole_count, __popc(ballot));
        base = __shfl_sync(0xffffffffu, base, leader);
        if (hole) {
            const int rank = __popc(ballot & ((1u << lane) - 1u));
            g_holes[base + rank] = gbase + p;
        }
    }
}

// ---------------------------------------------------------------------------
// 4) Hole fill over the compacted list (~2% of pixels): walk 4 axis
//    directions to nearest filled pixel, average. Writes only holes,
//    reads only filled pixels -> race-free in-place.
// ---------------------------------------------------------------------------
__global__ void fill_kernel(float* __restrict__ out) {
    const int n      = g_hole_count;
    const int stride = gridDim.x * blockDim.x;

    for (int j = blockIdx.x * blockDim.x + threadIdx.x; j < n; j += stride) {
        const int i = g_holes[j];
        const int b = i / HW;
        const int p = i - b * HW;
        const int y = p / Wn;
        const int x = p - y * Wn;

        const unsigned char* m  = g_mask + (size_t)b * HW;
        float*               o0 = out + (size_t)b * 2 * HW;
        float*               o1 = o0 + HW;

        float sx = 0.f, sy = 0.f;
        int   s  = 0;

        for (int xx = x - 1; xx >= 0; --xx) {            // left
            int q = y * Wn + xx;
            if (m[q]) { sx += o0[q]; sy += o1[q]; s++; break; }
        }
        for (int xx = x + 1; xx < Wn; ++xx) {            // right
            int q = y * Wn + xx;
            if (m[q]) { sx += o0[q]; sy += o1[q]; s++; break; }
        }
        for (int yy = y - 1; yy >= 0; --yy) {            // up
            int q = yy * Wn + x;
            if (m[q]) { sx += o0[q]; sy += o1[q]; s++; break; }
        }
        for (int yy = y + 1; yy < Hn; ++yy) {            // down
            int q = yy * Wn + x;
            if (m[q]) { sx += o0[q]; sy += o1[q]; s++; break; }
        }

        if (s > 0) {
            const float inv = 1.0f / (float)s;
            o0[y * Wn + x] = sx * inv;
            o1[y * Wn + x] = sy * inv;
        }
        // s == 0: out already 0 at holes (count==0 implies acc.xy==0)
    }
}

// ---------------------------------------------------------------------------
// Launch: per-batch slice pipeline through the L2-resident scratch (R6 shape).
// ---------------------------------------------------------------------------
extern "C" void kernel_launch(void* const* d_in, const int* in_sizes, int n_in,
                              void* d_out, int out_size) {
    const float* flow  = (const float*)d_in[0];   // (B, 2, H, W) fp32
    const float* depth = (const float*)d_in[1];   // (B, 1, H, W) fp32
    float*       out   = (float*)d_out;           // (B, 2, H, W) fp32

    // HW == 8100 * 256 exactly
    for (int b = 0; b < Bn; ++b) {
        zero_kernel<<<8100, 256>>>(b == 0 ? 1 : 0);
        splat_kernel<<<8100, 256>>>(flow + (size_t)b * 2 * HW,
                                    depth + (size_t)b * HW);
        normalize_kernel<<<8100, 256>>>(out + (size_t)b * 2 * HW, b * HW);
    }
    fill_kernel<<<2048, 256>>>(out);
}

// round 10
// speedup vs baseline: 1.3091x; 1.3091x over previous
#include <cuda_runtime.h>
#include <cuda_fp16.h>
#include <cstdint>

// Problem constants (fixed per reference)
#define Bn 8
#define Hn 1080
#define Wn 1920
constexpr int HW   = Hn * Wn;          // 2,073,600
constexpr int BHW  = Bn * HW;          // 16,588,800
constexpr int WP   = Wn / 2;           // 960 pair-cells per row
constexpr int LAT1 = Hn * WP;          // 1,036,800 pair-cells per parity lattice

// Per-slice pair-cell lattices (REUSED for all 8 batches -> L2-resident):
// each 16B cell = [vx0,vy0,w0,pad | vx1,vy1,w1,pad] (8 x f16)   [R6 layout]
// Parity 0 (even): pair k covers corners (2k, 2k+1)
// Parity 1 (odd):  pair k covers corners (2k+1, 2k+2)
__device__ float4        g_lat[2 * LAT1];   // 33.2 MB — fits L2 (126 MB)
__device__ unsigned char g_mask[BHW];       // count>0 flag (whole image)
__device__ int           g_holes[BHW];      // compacted hole indices (global index)
__device__ int           g_hole_count;

// --- bit reinterpretation helpers (header-portable) ------------------------
__device__ __forceinline__ unsigned h2_to_u32(__half2 h) {
    union { __half2 h; unsigned u; } cvt; cvt.h = h; return cvt.u;
}
__device__ __forceinline__ __half2 u32_to_h2(unsigned u) {
    union { unsigned u; __half2 h; } cvt; cvt.u = u; return cvt.h;
}

// One 16B vectorized f16x2 reduction: deposits (vx,vy,w) to TWO adjacent corners.
__device__ __forceinline__ void red_add_v4_f16x2(float4* p, unsigned r0, unsigned r1,
                                                 unsigned r2, unsigned r3) {
    asm volatile("red.global.add.noftz.v4.f16x2 [%0], {%1, %2, %3, %4};"
                 :: "l"(p), "r"(r0), "r"(r1), "r"(r2), "r"(r3) : "memory");
}

// ---------------------------------------------------------------------------
// 1) Zero the slice lattices (+ hole counter once per replay).
//    Full-line writes restore L2 residency of the slot (R7 lesson: required).
//    Grid covers 2*LAT1 == HW exactly (8100 x 256).
// ---------------------------------------------------------------------------
__global__ void zero_kernel(int reset_counter) {
    int i = blockIdx.x * blockDim.x + threadIdx.x;
    g_lat[i] = make_float4(0.f, 0.f, 0.f, 0.f);
    if (reset_counter && i == 0) g_hole_count = 0;
}

// ---------------------------------------------------------------------------
// 2) Forward splat for ONE batch slice, TWO pixels per thread (same row:
//    W is even). Vectorized float2 loads cut LSU load issues per pixel from
//    3 to 1.5; REDs stay at 2/pixel (proven floor).
// ---------------------------------------------------------------------------
__device__ __forceinline__ void splat_one(int x, int y, float fx, float fy, float w) {
    const float x2 = (float)x + fx;
    const float y2 = (float)y + fy;

    // Invalid pixels deposit exactly 0 in the reference -> skip.
    if (!(x2 >= 0.0f && x2 <= (float)(Wn - 1) &&
          y2 >= 0.0f && y2 <= (float)(Hn - 1)))
        return;

    const float vx = -fx * w;
    const float vy = -fy * w;

    // floor == trunc (non-negative by validity check)
    const int ixL = (int)x2;
    const int iyT = (int)y2;
    const int ixR = min(ixL + 1, Wn - 1);
    const int iyB = min(iyT + 1, Hn - 1);

    // Payload: lo half -> corner ixL, hi half -> corner ixR.
    // ixR==ixL (x2 == W-1 exactly): double lo payload, zero hi
    // (rn(2v) == 2*rn(v) in f16, bit-identical to two adds).
    const bool  dup = (ixR == ixL);
    const float m   = dup ? 2.0f : 1.0f;

    const unsigned r0 = h2_to_u32(__floats2half2_rn(vx * m, vy * m));
    const unsigned r1 = h2_to_u32(__floats2half2_rn(w * m, 0.0f));
    const unsigned r2 = dup ? 0u : h2_to_u32(__floats2half2_rn(vx, vy));
    const unsigned r3 = dup ? 0u : h2_to_u32(__floats2half2_rn(w, 0.0f));

    const int s  = ixL & 1;        // lattice parity
    const int kp = ixL >> 1;       // pair index

    float4* lat = g_lat + (size_t)s * LAT1 + kp;
    red_add_v4_f16x2(lat + iyT * WP, r0, r1, r2, r3);
    red_add_v4_f16x2(lat + iyB * WP, r0, r1, r2, r3);
}

__global__ void splat_kernel(const float* __restrict__ flow,
                             const float* __restrict__ depth) {
    const int t  = blockIdx.x * blockDim.x + threadIdx.x;   // [0, HW/2)
    const int p2 = t * 2;                                    // even pixel index
    const int y  = p2 / Wn;
    const int x  = p2 - y * Wn;                              // even, pair in-row

    // Vectorized loads: 8B each (both pixels at once).
    const float2 fx01 = *(const float2*)(flow + p2);
    const float2 fy01 = *(const float2*)(flow + HW + p2);
    const float2 d01  = *(const float2*)(depth + p2);

    splat_one(x,     y, fx01.x, fy01.x, d01.x);
    splat_one(x + 1, y, fx01.y, fy01.y, d01.y);
}

// ---------------------------------------------------------------------------
// 3) Normalize ONE batch slice: gather even+odd lattice halves per pixel,
//    divide, write out slice, record mask, compact holes (global indices).
// ---------------------------------------------------------------------------
__global__ void normalize_kernel(float* __restrict__ out, int gbase) {
    const int p = blockIdx.x * blockDim.x + threadIdx.x;   // [0, HW)
    const int y = p / Wn;
    const int x = p - y * Wn;

    const uint2* lat2 = (const uint2*)g_lat;   // one uint2 = one 8B half-cell
    const size_t rowc = (size_t)y * WP;

    // Even-lattice contribution: pair x>>1, half x&1
    const uint2 e = lat2[(rowc + (x >> 1)) * 2 + (x & 1)];
    const float2 xyE = __half22float2(u32_to_h2(e.x));
    const float  wE  = __low2float(u32_to_h2(e.y));

    // Odd-lattice contribution: covers x >= 1
    float2 xyO = make_float2(0.f, 0.f);
    float  wO  = 0.f;
    if (x > 0) {
        const int xo = x - 1;
        const uint2 o = lat2[((size_t)LAT1 + rowc + (xo >> 1)) * 2 + (xo & 1)];
        xyO = __half22float2(u32_to_h2(o.x));
        wO  = __low2float(u32_to_h2(o.y));
    }

    const float cnt  = wE + wO;
    const bool  hole = !(cnt > 0.0f);
    const float inv  = 1.0f / (hole ? 1.0f : cnt);

    out[p]      = (xyE.x + xyO.x) * inv;
    out[HW + p] = (xyE.y + xyO.y) * inv;
    g_mask[gbase + p] = hole ? 0 : 1;

    // Compact hole indices: one atomicAdd per warp.
    const unsigned ballot = __ballot_sync(0xffffffffu, hole);
    if (ballot) {
        const int lane   = threadIdx.x & 31;
        const int leader = __ffs(ballot) - 1;
        int base = 0;
        if (lane == leader) base = atomicAdd(&g_hole_count, __popc(ballot));
        base = __shfl_sync(0xffffffffu, base, leader);
        if (hole) {
            const int rank = __popc(ballot & ((1u << lane) - 1u));
            g_holes[base + rank] = gbase + p;
        }
    }
}

// ---------------------------------------------------------------------------
// 4) Hole fill over the compacted list (~2% of pixels): walk 4 axis
//    directions to nearest filled pixel, average. Writes only holes,
//    reads only filled pixels -> race-free in-place.
// ---------------------------------------------------------------------------
__global__ void fill_kernel(float* __restrict__ out) {
    const int n      = g_hole_count;
    const int stride = gridDim.x * blockDim.x;

    for (int j = blockIdx.x * blockDim.x + threadIdx.x; j < n; j += stride) {
        const int i = g_holes[j];
        const int b = i / HW;
        const int p = i - b * HW;
        const int y = p / Wn;
        const int x = p - y * Wn;

        const unsigned char* m  = g_mask + (size_t)b * HW;
        float*               o0 = out + (size_t)b * 2 * HW;
        float*               o1 = o0 + HW;

        float sx = 0.f, sy = 0.f;
        int   s  = 0;

        for (int xx = x - 1; xx >= 0; --xx) {            // left
            int q = y * Wn + xx;
            if (m[q]) { sx += o0[q]; sy += o1[q]; s++; break; }
        }
        for (int xx = x + 1; xx < Wn; ++xx) {            // right
            int q = y * Wn + xx;
            if (m[q]) { sx += o0[q]; sy += o1[q]; s++; break; }
        }
        for (int yy = y - 1; yy >= 0; --yy) {            // up
            int q = yy * Wn + x;
            if (m[q]) { sx += o0[q]; sy += o1[q]; s++; break; }
        }
        for (int yy = y + 1; yy < Hn; ++yy) {            // down
            int q = yy * Wn + x;
            if (m[q]) { sx += o0[q]; sy += o1[q]; s++; break; }
        }

        if (s > 0) {
            const float inv = 1.0f / (float)s;
            o0[y * Wn + x] = sx * inv;
            o1[y * Wn + x] = sy * inv;
        }
        // s == 0: out already 0 at holes (count==0 implies acc.xy==0)
    }
}

// ---------------------------------------------------------------------------
// Launch: per-batch slice pipeline through the L2-resident scratch (R6 shape).
// ---------------------------------------------------------------------------
extern "C" void kernel_launch(void* const* d_in, const int* in_sizes, int n_in,
                              void* d_out, int out_size) {
    const float* flow  = (const float*)d_in[0];   // (B, 2, H, W) fp32
    const float* depth = (const float*)d_in[1];   // (B, 1, H, W) fp32
    float*       out   = (float*)d_out;           // (B, 2, H, W) fp32

    for (int b = 0; b < Bn; ++b) {
        zero_kernel<<<8100, 256>>>(b == 0 ? 1 : 0);           // HW cells exact
        splat_kernel<<<4050, 256>>>(flow + (size_t)b * 2 * HW,
                                    depth + (size_t)b * HW);  // HW/2 threads exact
        normalize_kernel<<<8100, 256>>>(out + (size_t)b * 2 * HW, b * HW);
    }
    fill_kernel<<<2048, 256>>>(out);
}

// round 11
// speedup vs baseline: 1.3380x; 1.0221x over previous
#include <cuda_runtime.h>
#include <cuda_fp16.h>
#include <cstdint>

// Problem constants (fixed per reference)
#define Bn 8
#define Hn 1080
#define Wn 1920
constexpr int HW   = Hn * Wn;          // 2,073,600
constexpr int BHW  = Bn * HW;          // 16,588,800
constexpr int WP   = Wn / 2;           // 960 pair-cells per row
constexpr int LAT1 = Hn * WP;          // 1,036,800 pair-cells per parity lattice

// Per-slice pair-cell lattices (REUSED for all 8 batches -> L2-resident):
// each 16B cell = [vx0,vy0,w0,pad | vx1,vy1,w1,pad] (8 x f16)   [R6 layout]
// Parity 0 (even): pair k covers corners (2k, 2k+1)
// Parity 1 (odd):  pair k covers corners (2k+1, 2k+2)
__device__ float4        g_lat[2 * LAT1];   // 33.2 MB — fits L2 (126 MB)
__device__ unsigned char g_mask[BHW];       // count>0 flag (whole image)
__device__ int           g_holes[BHW];      // compacted hole indices (global index)
__device__ int           g_hole_count;

// --- bit reinterpretation helpers (header-portable) ------------------------
__device__ __forceinline__ unsigned h2_to_u32(__half2 h) {
    union { __half2 h; unsigned u; } cvt; cvt.h = h; return cvt.u;
}
__device__ __forceinline__ __half2 u32_to_h2(unsigned u) {
    union { unsigned u; __half2 h; } cvt; cvt.u = u; return cvt.h;
}

// One 16B vectorized f16x2 reduction: deposits (vx,vy,w) to TWO adjacent corners.
__device__ __forceinline__ void red_add_v4_f16x2(float4* p, unsigned r0, unsigned r1,
                                                 unsigned r2, unsigned r3) {
    asm volatile("red.global.add.noftz.v4.f16x2 [%0], {%1, %2, %3, %4};"
                 :: "l"(p), "r"(r0), "r"(r1), "r"(r2), "r"(r3) : "memory");
}

// ---------------------------------------------------------------------------
// 1) Zero the slice lattices (+ hole counter once per replay).
//    Full-line writes restore L2 residency of the slot (R7 lesson: required).
//    2 cells per thread: grid 4050 x 256 covers 2*LAT1 == HW cells exactly.
// ---------------------------------------------------------------------------
__global__ void zero_kernel(int reset_counter) {
    int i = (blockIdx.x * blockDim.x + threadIdx.x) * 2;
    const float4 z = make_float4(0.f, 0.f, 0.f, 0.f);
    g_lat[i]     = z;
    g_lat[i + 1] = z;
    if (reset_counter && i == 0) g_hole_count = 0;
}

// ---------------------------------------------------------------------------
// 2) Forward splat for ONE batch slice, TWO pixels per thread (same row:
//    W is even). Vectorized float2 loads; REDs at 2/pixel (proven floor).
// ---------------------------------------------------------------------------
__device__ __forceinline__ void splat_one(int x, int y, float fx, float fy, float w) {
    const float x2 = (float)x + fx;
    const float y2 = (float)y + fy;

    // Invalid pixels deposit exactly 0 in the reference -> skip.
    if (!(x2 >= 0.0f && x2 <= (float)(Wn - 1) &&
          y2 >= 0.0f && y2 <= (float)(Hn - 1)))
        return;

    const float vx = -fx * w;
    const float vy = -fy * w;

    // floor == trunc (non-negative by validity check)
    const int ixL = (int)x2;
    const int iyT = (int)y2;
    const int ixR = min(ixL + 1, Wn - 1);
    const int iyB = min(iyT + 1, Hn - 1);

    // Payload: lo half -> corner ixL, hi half -> corner ixR.
    // ixR==ixL (x2 == W-1 exactly): double lo payload, zero hi
    // (rn(2v) == 2*rn(v) in f16, bit-identical to two adds).
    const bool  dup = (ixR == ixL);
    const float m   = dup ? 2.0f : 1.0f;

    const unsigned r0 = h2_to_u32(__floats2half2_rn(vx * m, vy * m));
    const unsigned r1 = h2_to_u32(__floats2half2_rn(w * m, 0.0f));
    const unsigned r2 = dup ? 0u : h2_to_u32(__floats2half2_rn(vx, vy));
    const unsigned r3 = dup ? 0u : h2_to_u32(__floats2half2_rn(w, 0.0f));

    const int s  = ixL & 1;        // lattice parity
    const int kp = ixL >> 1;       // pair index

    float4* lat = g_lat + (size_t)s * LAT1 + kp;
    red_add_v4_f16x2(lat + iyT * WP, r0, r1, r2, r3);
    red_add_v4_f16x2(lat + iyB * WP, r0, r1, r2, r3);
}

__global__ void splat_kernel(const float* __restrict__ flow,
                             const float* __restrict__ depth) {
    const int t  = blockIdx.x * blockDim.x + threadIdx.x;   // [0, HW/2)
    const int p2 = t * 2;                                    // even pixel index
    const int y  = p2 / Wn;
    const int x  = p2 - y * Wn;                              // even, pair in-row

    const float2 fx01 = *(const float2*)(flow + p2);
    const float2 fy01 = *(const float2*)(flow + HW + p2);
    const float2 d01  = *(const float2*)(depth + p2);

    splat_one(x,     y, fx01.x, fy01.x, d01.x);
    splat_one(x + 1, y, fx01.y, fy01.y, d01.y);
}

// ---------------------------------------------------------------------------
// 3) Normalize ONE batch slice, TWO pixels per thread.
//    Pixel pair (2k, 2k+1): even lattice = one 16B cell load (pair k);
//    odd lattice = hi half of pair k-1 + lo half of pair k (two 8B loads).
//    Vectorized float2 out stores, 2-byte mask store, merged-ballot
//    compaction (one atomicAdd per warp).
// ---------------------------------------------------------------------------
__global__ void normalize_kernel(float* __restrict__ out, int gbase) {
    const int t  = blockIdx.x * blockDim.x + threadIdx.x;   // [0, HW/2)
    const int p2 = t * 2;
    const int y  = p2 / Wn;
    const int x  = p2 - y * Wn;       // even
    const int k  = x >> 1;            // pair index in row

    const size_t rowc = (size_t)y * WP;

    // Even lattice: one 16B cell -> both pixels' even contributions.
    const uint4 e = ((const uint4*)g_lat)[rowc + k];
    const float2 xyE0 = __half22float2(u32_to_h2(e.x));
    const float  wE0  = __low2float(u32_to_h2(e.y));
    const float2 xyE1 = __half22float2(u32_to_h2(e.z));
    const float  wE1  = __low2float(u32_to_h2(e.w));

    // Odd lattice:
    //   pixel x   (x>0): xo=x-1 odd -> hi half of pair k-1
    //   pixel x+1      : xo=x   even -> lo half of pair k
    const uint2* latO = (const uint2*)(g_lat + (size_t)LAT1);   // 8B half-cells
    float2 xyO0 = make_float2(0.f, 0.f);
    float  wO0  = 0.f;
    if (x > 0) {
        const uint2 oh = latO[((rowc + k - 1) << 1) | 1];
        xyO0 = __half22float2(u32_to_h2(oh.x));
        wO0  = __low2float(u32_to_h2(oh.y));
    }
    const uint2 ol = latO[(rowc + k) << 1];
    const float2 xyO1 = __half22float2(u32_to_h2(ol.x));
    const float  wO1  = __low2float(u32_to_h2(ol.y));

    const float cnt0 = wE0 + wO0;
    const float cnt1 = wE1 + wO1;
    const bool  h0   = !(cnt0 > 0.0f);
    const bool  h1   = !(cnt1 > 0.0f);
    const float inv0 = 1.0f / (h0 ? 1.0f : cnt0);
    const float inv1 = 1.0f / (h1 ? 1.0f : cnt1);

    *(float2*)(out + p2)      = make_float2((xyE0.x + xyO0.x) * inv0,
                                            (xyE1.x + xyO1.x) * inv1);
    *(float2*)(out + HW + p2) = make_float2((xyE0.y + xyO0.y) * inv0,
                                            (xyE1.y + xyO1.y) * inv1);
    *(unsigned short*)(g_mask + gbase + p2) =
        (unsigned short)((h0 ? 0 : 1) | ((h1 ? 0 : 1) << 8));

    // Merged hole compaction: one atomicAdd per warp for both sub-ballots.
    const unsigned b0 = __ballot_sync(0xffffffffu, h0);
    const unsigned b1 = __ballot_sync(0xffffffffu, h1);
    if (b0 | b1) {
        const int lane = threadIdx.x & 31;
        const int total = __popc(b0) + __popc(b1);
        int base = 0;
        if (lane == __ffs(b0 | b1) - 1) base = atomicAdd(&g_hole_count, total);
        base = __shfl_sync(0xffffffffu, base, __ffs(b0 | b1) - 1);
        const unsigned below = (1u << lane) - 1u;
        if (h0) g_holes[base + __popc(b0 & below)] = gbase + p2;
        if (h1) g_holes[base + __popc(b0) + __popc(b1 & below)] = gbase + p2 + 1;
    }
}

// ---------------------------------------------------------------------------
// 4) Hole fill over the compacted list (~2% of pixels): walk 4 axis
//    directions to nearest filled pixel, average. Writes only holes,
//    reads only filled pixels -> race-free in-place.
// ---------------------------------------------------------------------------
__global__ void fill_kernel(float* __restrict__ out) {
    const int n      = g_hole_count;
    const int stride = gridDim.x * blockDim.x;

    for (int j = blockIdx.x * blockDim.x + threadIdx.x; j < n; j += stride) {
        const int i = g_holes[j];
        const int b = i / HW;
        const int p = i - b * HW;
        const int y = p / Wn;
        const int x = p - y * Wn;

        const unsigned char* m  = g_mask + (size_t)b * HW;
        float*               o0 = out + (size_t)b * 2 * HW;
        float*               o1 = o0 + HW;

        float sx = 0.f, sy = 0.f;
        int   s  = 0;

        for (int xx = x - 1; xx >= 0; --xx) {            // left
            int q = y * Wn + xx;
            if (m[q]) { sx += o0[q]; sy += o1[q]; s++; break; }
        }
        for (int xx = x + 1; xx < Wn; ++xx) {            // right
            int q = y * Wn + xx;
            if (m[q]) { sx += o0[q]; sy += o1[q]; s++; break; }
        }
        for (int yy = y - 1; yy >= 0; --yy) {            // up
            int q = yy * Wn + x;
            if (m[q]) { sx += o0[q]; sy += o1[q]; s++; break; }
        }
        for (int yy = y + 1; yy < Hn; ++yy) {            // down
            int q = yy * Wn + x;
            if (m[q]) { sx += o0[q]; sy += o1[q]; s++; break; }
        }

        if (s > 0) {
            const float inv = 1.0f / (float)s;
            o0[y * Wn + x] = sx * inv;
            o1[y * Wn + x] = sy * inv;
        }
        // s == 0: out already 0 at holes (count==0 implies acc.xy==0)
    }
}

// ---------------------------------------------------------------------------
// Launch: per-batch slice pipeline through the L2-resident scratch (R6 shape).
// ---------------------------------------------------------------------------
extern "C" void kernel_launch(void* const* d_in, const int* in_sizes, int n_in,
                              void* d_out, int out_size) {
    const float* flow  = (const float*)d_in[0];   // (B, 2, H, W) fp32
    const float* depth = (const float*)d_in[1];   // (B, 1, H, W) fp32
    float*       out   = (float*)d_out;           // (B, 2, H, W) fp32

    for (int b = 0; b < Bn; ++b) {
        zero_kernel<<<4050, 256>>>(b == 0 ? 1 : 0);           // HW cells, 2/thread
        splat_kernel<<<4050, 256>>>(flow + (size_t)b * 2 * HW,
                                    depth + (size_t)b * HW);  // HW/2 threads exact
        normalize_kernel<<<4050, 256>>>(out + (size_t)b * 2 * HW, b * HW);
    }
    fill_kernel<<<2048, 256>>>(out);
}

// round 12
// speedup vs baseline: 1.5337x; 1.1462x over previous
#include <cuda_runtime.h>
#include <cuda_fp16.h>
#include <cstdint>

// Problem constants (fixed per reference)
#define Bn 8
#define Hn 1080
#define Wn 1920
constexpr int HW   = Hn * Wn;          // 2,073,600
constexpr int BHW  = Bn * HW;          // 16,588,800
constexpr int WP   = Wn / 2;           // 960 pair-cells per row
constexpr int LAT1 = Hn * WP;          // 1,036,800 pair-cells per parity lattice

// Per-slice pair-cell lattices (REUSED for all 8 batches -> L2-resident):
// each 16B cell = [vx0,vy0,w0,pad | vx1,vy1,w1,pad] (8 x f16)   [R6 layout]
// Parity 0 (even): pair k covers corners (2k, 2k+1)
// Parity 1 (odd):  pair k covers corners (2k+1, 2k+2)
__device__ float4        g_lat[2 * LAT1];   // 33.2 MB — fits L2 (126 MB)
__device__ unsigned char g_mask[BHW];       // count>0 flag (whole image)
__device__ int           g_holes[BHW];      // compacted hole indices (global index)
__device__ int           g_hole_count;

// --- bit reinterpretation helpers (header-portable) ------------------------
__device__ __forceinline__ unsigned h2_to_u32(__half2 h) {
    union { __half2 h; unsigned u; } cvt; cvt.h = h; return cvt.u;
}
__device__ __forceinline__ __half2 u32_to_h2(unsigned u) {
    union { unsigned u; __half2 h; } cvt; cvt.u = u; return cvt.h;
}

// One 16B vectorized f16x2 reduction: deposits (vx,vy,w) to TWO adjacent corners.
__device__ __forceinline__ void red_add_v4_f16x2(float4* p, unsigned r0, unsigned r1,
                                                 unsigned r2, unsigned r3) {
    asm volatile("red.global.add.noftz.v4.f16x2 [%0], {%1, %2, %3, %4};"
                 :: "l"(p), "r"(r0), "r"(r1), "r"(r2), "r"(r3) : "memory");
}

// ---------------------------------------------------------------------------
// 1) Zero the slice lattices (+ hole counter once per replay).
//    PROVEN form (R6/R10): 1 float4 per thread, fully coalesced, 7.9us.
//    Full-line writes restore L2 residency of the slot (R7 lesson: required).
//    Grid covers 2*LAT1 == HW cells exactly (8100 x 256).
// ---------------------------------------------------------------------------
__global__ void zero_kernel(int reset_counter) {
    int i = blockIdx.x * blockDim.x + threadIdx.x;
    g_lat[i] = make_float4(0.f, 0.f, 0.f, 0.f);
    if (reset_counter && i == 0) g_hole_count = 0;
}

// ---------------------------------------------------------------------------
// 2) Forward splat for ONE batch slice, TWO pixels per thread (same row:
//    W is even). Vectorized float2 loads; REDs at 2/pixel (proven floor).
// ---------------------------------------------------------------------------
__device__ __forceinline__ void splat_one(int x, int y, float fx, float fy, float w) {
    const float x2 = (float)x + fx;
    const float y2 = (float)y + fy;

    // Invalid pixels deposit exactly 0 in the reference -> skip.
    if (!(x2 >= 0.0f && x2 <= (float)(Wn - 1) &&
          y2 >= 0.0f && y2 <= (float)(Hn - 1)))
        return;

    const float vx = -fx * w;
    const float vy = -fy * w;

    // floor == trunc (non-negative by validity check)
    const int ixL = (int)x2;
    const int iyT = (int)y2;
    const int ixR = min(ixL + 1, Wn - 1);
    const int iyB = min(iyT + 1, Hn - 1);

    // Payload: lo half -> corner ixL, hi half -> corner ixR.
    // ixR==ixL (x2 == W-1 exactly): double lo payload, zero hi
    // (rn(2v) == 2*rn(v) in f16, bit-identical to two adds).
    const bool  dup = (ixR == ixL);
    const float m   = dup ? 2.0f : 1.0f;

    const unsigned r0 = h2_to_u32(__floats2half2_rn(vx * m, vy * m));
    const unsigned r1 = h2_to_u32(__floats2half2_rn(w * m, 0.0f));
    const unsigned r2 = dup ? 0u : h2_to_u32(__floats2half2_rn(vx, vy));
    const unsigned r3 = dup ? 0u : h2_to_u32(__floats2half2_rn(w, 0.0f));

    const int s  = ixL & 1;        // lattice parity
    const int kp = ixL >> 1;       // pair index

    float4* lat = g_lat + (size_t)s * LAT1 + kp;
    red_add_v4_f16x2(lat + iyT * WP, r0, r1, r2, r3);
    red_add_v4_f16x2(lat + iyB * WP, r0, r1, r2, r3);
}

__global__ void splat_kernel(const float* __restrict__ flow,
                             const float* __restrict__ depth) {
    const int t  = blockIdx.x * blockDim.x + threadIdx.x;   // [0, HW/2)
    const int p2 = t * 2;                                    // even pixel index
    const int y  = p2 / Wn;
    const int x  = p2 - y * Wn;                              // even, pair in-row

    const float2 fx01 = *(const float2*)(flow + p2);
    const float2 fy01 = *(const float2*)(flow + HW + p2);
    const float2 d01  = *(const float2*)(depth + p2);

    splat_one(x,     y, fx01.x, fy01.x, d01.x);
    splat_one(x + 1, y, fx01.y, fy01.y, d01.y);
}

// ---------------------------------------------------------------------------
// 3) Normalize ONE batch slice, FOUR pixels per thread (x0 = 4t mod row,
//    W % 4 == 0 so all 4 share a row).
//    Even lattice:  pairs k, k+1          -> two 16B loads
//    Odd  lattice:  pair k-1 hi (8B), pair k full (16B), pair k+1 lo (8B)
//      corner c in odd lattice: c odd -> pair (c-1)/2 lo; c even -> pair c/2-1 hi
//      pixels x0..x0+3 -> corners x0..x0+3 -> (k-1 hi), (k lo), (k hi), (k+1 lo)
//    Stores: two float4 out writes + one 4B mask word.
// ---------------------------------------------------------------------------
__global__ void normalize_kernel(float* __restrict__ out, int gbase) {
    const int t  = blockIdx.x * blockDim.x + threadIdx.x;   // [0, HW/4)
    const int p4 = t * 4;
    const int y  = p4 / Wn;
    const int x0 = p4 - y * Wn;       // multiple of 4
    const int k  = x0 >> 1;           // even-lattice pair index (even)

    const size_t rowc = (size_t)y * WP;
    const uint4* latE = (const uint4*)g_lat;
    const uint2* latO = (const uint2*)(g_lat + (size_t)LAT1);   // 8B half-cells

    // Even lattice: pairs k, k+1
    const uint4 e0 = latE[rowc + k];
    const uint4 e1 = latE[rowc + k + 1];

    // Odd lattice
    float2 xyO0 = make_float2(0.f, 0.f);
    float  wO0  = 0.f;
    if (x0 > 0) {
        const uint2 oh = latO[((rowc + k - 1) << 1) | 1];   // pair k-1 hi
        xyO0 = __half22float2(u32_to_h2(oh.x));
        wO0  = __low2float(u32_to_h2(oh.y));
    }
    const uint4 om = latE[(size_t)LAT1 + rowc + k];          // pair k full (lo+hi)
    const uint2 ol = latO[((rowc + k + 1) << 1)];            // pair k+1 lo

    // Per-pixel accumulate: pixel j uses even half + odd corner slot.
    float sxv[4], syv[4], cntv[4];
    // pixel 0: even e0 lo, odd = xyO0/wO0
    {
        const float2 xyE = __half22float2(u32_to_h2(e0.x));
        const float  wE  = __low2float(u32_to_h2(e0.y));
        sxv[0] = xyE.x + xyO0.x; syv[0] = xyE.y + xyO0.y; cntv[0] = wE + wO0;
    }
    // pixel 1: even e0 hi, odd = pair k lo (om.x/om.y)
    {
        const float2 xyE = __half22float2(u32_to_h2(e0.z));
        const float  wE  = __low2float(u32_to_h2(e0.w));
        const float2 xyO = __half22float2(u32_to_h2(om.x));
        const float  wO  = __low2float(u32_to_h2(om.y));
        sxv[1] = xyE.x + xyO.x; syv[1] = xyE.y + xyO.y; cntv[1] = wE + wO;
    }
    // pixel 2: even e1 lo, odd = pair k hi (om.z/om.w)
    {
        const float2 xyE = __half22float2(u32_to_h2(e1.x));
        const float  wE  = __low2float(u32_to_h2(e1.y));
        const float2 xyO = __half22float2(u32_to_h2(om.z));
        const float  wO  = __low2float(u32_to_h2(om.w));
        sxv[2] = xyE.x + xyO.x; syv[2] = xyE.y + xyO.y; cntv[2] = wE + wO;
    }
    // pixel 3: even e1 hi, odd = pair k+1 lo (ol)
    {
        const float2 xyE = __half22float2(u32_to_h2(e1.z));
        const float  wE  = __low2float(u32_to_h2(e1.w));
        const float2 xyO = __half22float2(u32_to_h2(ol.x));
        const float  wO  = __low2float(u32_to_h2(ol.y));
        sxv[3] = xyE.x + xyO.x; syv[3] = xyE.y + xyO.y; cntv[3] = wE + wO;
    }

    bool  h[4];
    float ox[4], oy[4];
    unsigned maskw = 0;
#pragma unroll
    for (int j = 0; j < 4; ++j) {
        h[j] = !(cntv[j] > 0.0f);
        const float inv = 1.0f / (h[j] ? 1.0f : cntv[j]);
        ox[j] = sxv[j] * inv;
        oy[j] = syv[j] * inv;
        maskw |= (h[j] ? 0u : 1u) << (j * 8);
    }

    *(float4*)(out + p4)      = make_float4(ox[0], ox[1], ox[2], ox[3]);
    *(float4*)(out + HW + p4) = make_float4(oy[0], oy[1], oy[2], oy[3]);
    *(unsigned*)(g_mask + gbase + p4) = maskw;

    // Merged hole compaction: one atomicAdd per warp for all four sub-ballots.
    const unsigned b0 = __ballot_sync(0xffffffffu, h[0]);
    const unsigned b1 = __ballot_sync(0xffffffffu, h[1]);
    const unsigned b2 = __ballot_sync(0xffffffffu, h[2]);
    const unsigned b3 = __ballot_sync(0xffffffffu, h[3]);
    const unsigned any = b0 | b1 | b2 | b3;
    if (any) {
        const int lane   = threadIdx.x & 31;
        const int leader = __ffs(any) - 1;
        const int total  = __popc(b0) + __popc(b1) + __popc(b2) + __popc(b3);
        int base = 0;
        if (lane == leader) base = atomicAdd(&g_hole_count, total);
        base = __shfl_sync(0xffffffffu, base, leader);
        const unsigned below = (1u << lane) - 1u;
        int off = base;
        if (h[0]) g_holes[off + __popc(b0 & below)] = gbase + p4;
        off += __popc(b0);
        if (h[1]) g_holes[off + __popc(b1 & below)] = gbase + p4 + 1;
        off += __popc(b1);
        if (h[2]) g_holes[off + __popc(b2 & below)] = gbase + p4 + 2;
        off += __popc(b2);
        if (h[3]) g_holes[off + __popc(b3 & below)] = gbase + p4 + 3;
    }
}

// ---------------------------------------------------------------------------
// 4) Hole fill over the compacted list (~2% of pixels): walk 4 axis
//    directions to nearest filled pixel, average. Writes only holes,
//    reads only filled pixels -> race-free in-place.
// ---------------------------------------------------------------------------
__global__ void fill_kernel(float* __restrict__ out) {
    const int n      = g_hole_count;
    const int stride = gridDim.x * blockDim.x;

    for (int j = blockIdx.x * blockDim.x + threadIdx.x; j < n; j += stride) {
        const int i = g_holes[j];
        const int b = i / HW;
        const int p = i - b * HW;
        const int y = p / Wn;
        const int x = p - y * Wn;

        const unsigned char* m  = g_mask + (size_t)b * HW;
        float*               o0 = out + (size_t)b * 2 * HW;
        float*               o1 = o0 + HW;

        float sx = 0.f, sy = 0.f;
        int   s  = 0;

        for (int xx = x - 1; xx >= 0; --xx) {            // left
            int q = y * Wn + xx;
            if (m[q]) { sx += o0[q]; sy += o1[q]; s++; break; }
        }
        for (int xx = x + 1; xx < Wn; ++xx) {            // right
            int q = y * Wn + xx;
            if (m[q]) { sx += o0[q]; sy += o1[q]; s++; break; }
        }
        for (int yy = y - 1; yy >= 0; --yy) {            // up
            int q = yy * Wn + x;
            if (m[q]) { sx += o0[q]; sy += o1[q]; s++; break; }
        }
        for (int yy = y + 1; yy < Hn; ++yy) {            // down
            int q = yy * Wn + x;
            if (m[q]) { sx += o0[q]; sy += o1[q]; s++; break; }
        }

        if (s > 0) {
            const float inv = 1.0f / (float)s;
            o0[y * Wn + x] = sx * inv;
            o1[y * Wn + x] = sy * inv;
        }
        // s == 0: out already 0 at holes (count==0 implies acc.xy==0)
    }
}

// ---------------------------------------------------------------------------
// Launch: per-batch slice pipeline through the L2-resident scratch (R6 shape).
// ---------------------------------------------------------------------------
extern "C" void kernel_launch(void* const* d_in, const int* in_sizes, int n_in,
                              void* d_out, int out_size) {
    const float* flow  = (const float*)d_in[0];   // (B, 2, H, W) fp32
    const float* depth = (const float*)d_in[1];   // (B, 1, H, W) fp32
    float*       out   = (float*)d_out;           // (B, 2, H, W) fp32

    for (int b = 0; b < Bn; ++b) {
        zero_kernel<<<8100, 256>>>(b == 0 ? 1 : 0);           // HW cells, 1/thread
        splat_kernel<<<4050, 256>>>(flow + (size_t)b * 2 * HW,
                                    depth + (size_t)b * HW);  // HW/2 threads
        normalize_kernel<<<2025, 256>>>(out + (size_t)b * 2 * HW, b * HW); // HW/4
    }
    fill_kernel<<<2048, 256>>>(out);
}

// round 13
// speedup vs baseline: 1.6036x; 1.0456x over previous
#include <cuda_runtime.h>
#include <cuda_fp16.h>
#include <cstdint>

// Problem constants (fixed per reference)
#define Bn 8
#define Hn 1080
#define Wn 1920
constexpr int HW   = Hn * Wn;          // 2,073,600
constexpr int BHW  = Bn * HW;          // 16,588,800
constexpr int WP   = Wn / 2;           // 960 pair-cells per row
constexpr int LAT1 = Hn * WP;          // 1,036,800 pair-cells per parity lattice

// PING-PONG pair-cell lattice slots. Slot s = [parity0 | parity1] lattices.
// 16B cell = [vx0,vy0,w0,pad | vx1,vy1,w1,pad] (8 x f16)   [R6 layout]
// Parity 0 (even): pair k covers corners (2k, 2k+1)
// Parity 1 (odd):  pair k covers corners (2k+1, 2k+2)
// Every slot is explicitly zeroed before every splat into it (replay-safe).
__device__ float4        g_lat[2 * 2 * LAT1];   // 66.4 MB (two slots)
__device__ unsigned char g_mask[BHW];           // count>0 flag (whole image)
__device__ int           g_holes[BHW];          // compacted hole indices
__device__ int           g_hole_count;

constexpr int NORM_BLOCKS = 2025;   // HW/4 threads @256
constexpr int ZERO_BLOCKS = 8100;   // HW cells  @256

// --- bit reinterpretation helpers (header-portable) ------------------------
__device__ __forceinline__ unsigned h2_to_u32(__half2 h) {
    union { __half2 h; unsigned u; } cvt; cvt.h = h; return cvt.u;
}
__device__ __forceinline__ __half2 u32_to_h2(unsigned u) {
    union { unsigned u; __half2 h; } cvt; cvt.u = u; return cvt.h;
}

// One 16B vectorized f16x2 reduction: deposits (vx,vy,w) to TWO adjacent corners.
__device__ __forceinline__ void red_add_v4_f16x2(float4* p, unsigned r0, unsigned r1,
                                                 unsigned r2, unsigned r3) {
    asm volatile("red.global.add.noftz.v4.f16x2 [%0], {%1, %2, %3, %4};"
                 :: "l"(p), "r"(r0), "r"(r1), "r"(r2), "r"(r3) : "memory");
}

// ---------------------------------------------------------------------------
// Zero one slot (1 float4/thread, proven coalesced form; restores L2 residency)
// ---------------------------------------------------------------------------
__global__ void zero_kernel(int slot, int reset_counter) {
    int i = blockIdx.x * blockDim.x + threadIdx.x;
    g_lat[(size_t)slot * 2 * LAT1 + i] = make_float4(0.f, 0.f, 0.f, 0.f);
    if (reset_counter && i == 0) g_hole_count = 0;
}

// ---------------------------------------------------------------------------
// Forward splat for ONE batch slice into slot, TWO pixels per thread.
// ---------------------------------------------------------------------------
__device__ __forceinline__ void splat_one(float4* slotBase, int x, int y,
                                          float fx, float fy, float w) {
    const float x2 = (float)x + fx;
    const float y2 = (float)y + fy;

    // Invalid pixels deposit exactly 0 in the reference -> skip.
    if (!(x2 >= 0.0f && x2 <= (float)(Wn - 1) &&
          y2 >= 0.0f && y2 <= (float)(Hn - 1)))
        return;

    const float vx = -fx * w;
    const float vy = -fy * w;

    // floor == trunc (non-negative by validity check)
    const int ixL = (int)x2;
    const int iyT = (int)y2;
    const int ixR = min(ixL + 1, Wn - 1);
    const int iyB = min(iyT + 1, Hn - 1);

    // lo half -> corner ixL, hi half -> corner ixR.
    // ixR==ixL (x2 == W-1 exactly): double lo payload, zero hi
    // (rn(2v) == 2*rn(v) in f16, bit-identical to two adds).
    const bool  dup = (ixR == ixL);
    const float m   = dup ? 2.0f : 1.0f;

    const unsigned r0 = h2_to_u32(__floats2half2_rn(vx * m, vy * m));
    const unsigned r1 = h2_to_u32(__floats2half2_rn(w * m, 0.0f));
    const unsigned r2 = dup ? 0u : h2_to_u32(__floats2half2_rn(vx, vy));
    const unsigned r3 = dup ? 0u : h2_to_u32(__floats2half2_rn(w, 0.0f));

    const int s  = ixL & 1;        // lattice parity
    const int kp = ixL >> 1;       // pair index

    float4* lat = slotBase + (size_t)s * LAT1 + kp;
    red_add_v4_f16x2(lat + iyT * WP, r0, r1, r2, r3);
    red_add_v4_f16x2(lat + iyB * WP, r0, r1, r2, r3);
}

__global__ void splat_kernel(const float* __restrict__ flow,
                             const float* __restrict__ depth, int slot) {
    const int t  = blockIdx.x * blockDim.x + threadIdx.x;   // [0, HW/2)
    const int p2 = t * 2;
    const int y  = p2 / Wn;
    const int x  = p2 - y * Wn;

    const float2 fx01 = *(const float2*)(flow + p2);
    const float2 fy01 = *(const float2*)(flow + HW + p2);
    const float2 d01  = *(const float2*)(depth + p2);

    float4* slotBase = g_lat + (size_t)slot * 2 * LAT1;
    splat_one(slotBase, x,     y, fx01.x, fy01.x, d01.x);
    splat_one(slotBase, x + 1, y, fx01.y, fy01.y, d01.y);
}

// ---------------------------------------------------------------------------
// Normalize body (4 pixels/thread, R12-proven). latS = slot base.
// ---------------------------------------------------------------------------
__device__ __forceinline__ void normalize_body(int t, const float4* latS,
                                               float* __restrict__ out, int gbase) {
    const int p4 = t * 4;
    const int y  = p4 / Wn;
    const int x0 = p4 - y * Wn;       // multiple of 4
    const int k  = x0 >> 1;           // even-lattice pair index (even)

    const size_t rowc = (size_t)y * WP;
    const uint4* latE = (const uint4*)latS;
    const uint2* latO = (const uint2*)(latS + (size_t)LAT1);   // 8B half-cells

    const uint4 e0 = latE[rowc + k];
    const uint4 e1 = latE[rowc + k + 1];

    float2 xyO0 = make_float2(0.f, 0.f);
    float  wO0  = 0.f;
    if (x0 > 0) {
        const uint2 oh = latO[((rowc + k - 1) << 1) | 1];   // pair k-1 hi
        xyO0 = __half22float2(u32_to_h2(oh.x));
        wO0  = __low2float(u32_to_h2(oh.y));
    }
    const uint4 om = latE[(size_t)LAT1 + rowc + k];          // odd pair k full
    const uint2 ol = latO[((rowc + k + 1) << 1)];            // odd pair k+1 lo

    float sxv[4], syv[4], cntv[4];
    {
        const float2 xyE = __half22float2(u32_to_h2(e0.x));
        const float  wE  = __low2float(u32_to_h2(e0.y));
        sxv[0] = xyE.x + xyO0.x; syv[0] = xyE.y + xyO0.y; cntv[0] = wE + wO0;
    }
    {
        const float2 xyE = __half22float2(u32_to_h2(e0.z));
        const float  wE  = __low2float(u32_to_h2(e0.w));
        const float2 xyO = __half22float2(u32_to_h2(om.x));
        const float  wO  = __low2float(u32_to_h2(om.y));
        sxv[1] = xyE.x + xyO.x; syv[1] = xyE.y + xyO.y; cntv[1] = wE + wO;
    }
    {
        const float2 xyE = __half22float2(u32_to_h2(e1.x));
        const float  wE  = __low2float(u32_to_h2(e1.y));
        const float2 xyO = __half22float2(u32_to_h2(om.z));
        const float  wO  = __low2float(u32_to_h2(om.w));
        sxv[2] = xyE.x + xyO.x; syv[2] = xyE.y + xyO.y; cntv[2] = wE + wO;
    }
    {
        const float2 xyE = __half22float2(u32_to_h2(e1.z));
        const float  wE  = __low2float(u32_to_h2(e1.w));
        const float2 xyO = __half22float2(u32_to_h2(ol.x));
        const float  wO  = __low2float(u32_to_h2(ol.y));
        sxv[3] = xyE.x + xyO.x; syv[3] = xyE.y + xyO.y; cntv[3] = wE + wO;
    }

    bool  h[4];
    float ox[4], oy[4];
    unsigned maskw = 0;
#pragma unroll
    for (int j = 0; j < 4; ++j) {
        h[j] = !(cntv[j] > 0.0f);
        const float inv = 1.0f / (h[j] ? 1.0f : cntv[j]);
        ox[j] = sxv[j] * inv;
        oy[j] = syv[j] * inv;
        maskw |= (h[j] ? 0u : 1u) << (j * 8);
    }

    *(float4*)(out + p4)      = make_float4(ox[0], ox[1], ox[2], ox[3]);
    *(float4*)(out + HW + p4) = make_float4(oy[0], oy[1], oy[2], oy[3]);
    *(unsigned*)(g_mask + gbase + p4) = maskw;

    const unsigned b0 = __ballot_sync(0xffffffffu, h[0]);
    const unsigned b1 = __ballot_sync(0xffffffffu, h[1]);
    const unsigned b2 = __ballot_sync(0xffffffffu, h[2]);
    const unsigned b3 = __ballot_sync(0xffffffffu, h[3]);
    const unsigned any = b0 | b1 | b2 | b3;
    if (any) {
        const int lane   = threadIdx.x & 31;
        const int leader = __ffs(any) - 1;
        const int total  = __popc(b0) + __popc(b1) + __popc(b2) + __popc(b3);
        int base = 0;
        if (lane == leader) base = atomicAdd(&g_hole_count, total);
        base = __shfl_sync(0xffffffffu, base, leader);
        const unsigned below = (1u << lane) - 1u;
        int off = base;
        if (h[0]) g_holes[off + __popc(b0 & below)] = gbase + p4;
        off += __popc(b0);
        if (h[1]) g_holes[off + __popc(b1 & below)] = gbase + p4 + 1;
        off += __popc(b1);
        if (h[2]) g_holes[off + __popc(b2 & below)] = gbase + p4 + 2;
        off += __popc(b2);
        if (h[3]) g_holes[off + __popc(b3 & below)] = gbase + p4 + 3;
    }
}

// ---------------------------------------------------------------------------
// Merged kernel: blocks [0, NORM_BLOCKS) normalize slice b-1 from slotNorm;
// blocks [NORM_BLOCKS, NORM_BLOCKS+ZERO_BLOCKS) zero slotZero for slice b+1.
// Slots differ -> no data race; block-level overlap of the two phases.
// ---------------------------------------------------------------------------
__global__ void merged_kernel(float* __restrict__ outPrev, int gbasePrev,
                              int slotNorm, int slotZero) {
    if (blockIdx.x < NORM_BLOCKS) {
        normalize_body(blockIdx.x * blockDim.x + threadIdx.x,
                       g_lat + (size_t)slotNorm * 2 * LAT1, outPrev, gbasePrev);
    } else {
        const int i = (blockIdx.x - NORM_BLOCKS) * blockDim.x + threadIdx.x;
        g_lat[(size_t)slotZero * 2 * LAT1 + i] = make_float4(0.f, 0.f, 0.f, 0.f);
    }
}

// Normalize-only kernel (final slice drain).
__global__ void norm_kernel(float* __restrict__ out, int gbase, int slot) {
    normalize_body(blockIdx.x * blockDim.x + threadIdx.x,
                   g_lat + (size_t)slot * 2 * LAT1, out, gbase);
}

// ---------------------------------------------------------------------------
// Hole fill over the compacted list (~2% of pixels).
// ---------------------------------------------------------------------------
__global__ void fill_kernel(float* __restrict__ out) {
    const int n      = g_hole_count;
    const int stride = gridDim.x * blockDim.x;

    for (int j = blockIdx.x * blockDim.x + threadIdx.x; j < n; j += stride) {
        const int i = g_holes[j];
        const int b = i / HW;
        const int p = i - b * HW;
        const int y = p / Wn;
        const int x = p - y * Wn;

        const unsigned char* m  = g_mask + (size_t)b * HW;
        float*               o0 = out + (size_t)b * 2 * HW;
        float*               o1 = o0 + HW;

        float sx = 0.f, sy = 0.f;
        int   s  = 0;

        for (int xx = x - 1; xx >= 0; --xx) {            // left
            int q = y * Wn + xx;
            if (m[q]) { sx += o0[q]; sy += o1[q]; s++; break; }
        }
        for (int xx = x + 1; xx < Wn; ++xx) {            // right
            int q = y * Wn + xx;
            if (m[q]) { sx += o0[q]; sy += o1[q]; s++; break; }
        }
        for (int yy = y - 1; yy >= 0; --yy) {            // up
            int q = yy * Wn + x;
            if (m[q]) { sx += o0[q]; sy += o1[q]; s++; break; }
        }
        for (int yy = y + 1; yy < Hn; ++yy) {            // down
            int q = yy * Wn + x;
            if (m[q]) { sx += o0[q]; sy += o1[q]; s++; break; }
        }

        if (s > 0) {
            const float inv = 1.0f / (float)s;
            o0[y * Wn + x] = sx * inv;
            o1[y * Wn + x] = sy * inv;
        }
        // s == 0: out already 0 at holes (count==0 implies acc.xy==0)
    }
}

// ---------------------------------------------------------------------------
// Launch: ping-pong pipeline.
//   zero(slot0); for b: splat(b -> slot b&1); merged(norm b <- slot b&1,
//   zero slot (b+1)&1); final norm(7); fill.
// ---------------------------------------------------------------------------
extern "C" void kernel_launch(void* const* d_in, const int* in_sizes, int n_in,
                              void* d_out, int out_size) {
    const float* flow  = (const float*)d_in[0];   // (B, 2, H, W) fp32
    const float* depth = (const float*)d_in[1];   // (B, 1, H, W) fp32
    float*       out   = (float*)d_out;           // (B, 2, H, W) fp32

    zero_kernel<<<ZERO_BLOCKS, 256>>>(0, 1);      // slot0 + reset hole counter

    for (int b = 0; b < Bn; ++b) {
        splat_kernel<<<4050, 256>>>(flow + (size_t)b * 2 * HW,
                                    depth + (size_t)b * HW, b & 1);
        if (b < Bn - 1) {
            // normalize slice b from slot b&1; zero slot (b+1)&1 for next splat
            merged_kernel<<<NORM_BLOCKS + ZERO_BLOCKS, 256>>>(
                out + (size_t)b * 2 * HW, b * HW, b & 1, (b + 1) & 1);
        }
    }
    norm_kernel<<<NORM_BLOCKS, 256>>>(out + (size_t)(Bn - 1) * 2 * HW,
                                      (Bn - 1) * HW, (Bn - 1) & 1);
    fill_kernel<<<2048, 256>>>(out);
}